// round 11
// baseline (speedup 1.0000x reference)
#include <cuda_runtime.h>
#include <cuda_bf16.h>
#include <math.h>
#include <stdint.h>

#define BB 1024
#define TT 70
#define HH 150
#define DIN 300
#define G4 600
#define BT (BB*TT)
#define DEPTH 5
#define KPA 640           // A2: [Ah(320) | Al(320)]
#define KPB 960           // B2: [Bh | Bl | Bh]

typedef unsigned long long ull;

// ---------------- scratch ----------------------------------------------------
__device__ float g_xz[2][BT][G4];
__device__ int   g_lens[BB];
__device__ int   g_coff[BB];
__device__ int   g_cnt[32*32];
__device__ int   g_cmap[BT];
__device__ int   g_M;
__device__ unsigned short g_A2[BT][KPA];            // split-bf16 activations
__device__ unsigned short g_B2[DEPTH][2][640][KPB]; // xz weights (split-bf16, W^T)
__device__ unsigned short g_hA[2][BB][512];         // h in interleaved-3 operand form
__device__ unsigned short g_WhB[DEPTH][2][600][512];// recurrent weights interleaved-3

// ---------------- helpers -----------------------------------------------------
__device__ __forceinline__ float sigmf(float x) {
    return __fdividef(1.f, 1.f + __expf(-x));
}
__device__ __forceinline__ float tanhff(float x) {
    return 1.f - __fdividef(2.f, __expf(2.f * x) + 1.f);
}
__device__ __forceinline__ void cp16(uint32_t smem_dst, const void* gsrc) {
    asm volatile("cp.async.ca.shared.global [%0], [%1], 16;"
                 :: "r"(smem_dst), "l"(gsrc) : "memory");
}
__device__ __forceinline__ uint32_t smem_u32(const void* p) {
    uint32_t a;
    asm("{ .reg .u64 t; cvta.to.shared.u64 t, %1; cvt.u32.u64 %0, t; }"
        : "=r"(a) : "l"(p));
    return a;
}
#define SWZ(o) ((o) ^ (((o) >> 3) & 0x70))

#define LDSM4(r0,r1,r2,r3,addr) \
    asm volatile("ldmatrix.sync.aligned.m8n8.x4.shared.b16 {%0,%1,%2,%3}, [%4];" \
        : "=r"(r0), "=r"(r1), "=r"(r2), "=r"(r3) : "r"(addr))

#define MMA16816(c,a,b0,b1) \
    asm volatile("mma.sync.aligned.m16n8k16.row.col.f32.bf16.bf16.f32 " \
        "{%0,%1,%2,%3}, {%4,%5,%6,%7}, {%8,%9}, {%0,%1,%2,%3};" \
        : "+f"((c)[0]), "+f"((c)[1]), "+f"((c)[2]), "+f"((c)[3]) \
        : "r"((a)[0]), "r"((a)[1]), "r"((a)[2]), "r"((a)[3]), "r"(b0), "r"(b1))

__device__ __forceinline__ unsigned short bfbits(__nv_bfloat16 h) {
    return *(unsigned short*)&h;
}
__device__ __forceinline__ float bf2f(unsigned short u) {
    __nv_bfloat16 h = *(__nv_bfloat16*)&u;
    return __bfloat162float(h);
}

// ---------------- lens + scan + cmap -----------------------------------------
__global__ void build_cmap(const int* __restrict__ mask) {
    __shared__ int sl[1024];
    int b = threadIdx.x;
    int s = 0;
    #pragma unroll
    for (int t = 0; t < TT; t++) s += mask[b * TT + t];
    g_lens[b] = s;
    sl[b] = s;
    g_cnt[b] = 0;
    __syncthreads();
    for (int d = 1; d < 1024; d <<= 1) {
        int v = 0;
        if (b >= d) v = sl[b - d];
        __syncthreads();
        if (b >= d) sl[b] += v;
        __syncthreads();
    }
    int excl = sl[b] - s;
    g_coff[b] = excl;
    for (int t = 0; t < s; t++) g_cmap[excl + t] = b * TT + t;
    if (b == 1023) g_M = sl[1023];
}

// ---------------- operand prep ------------------------------------------------
// A2[m] = [Ah(320) | Al(320)] from X (layer 0 only)
__global__ void prep_a2(const float* __restrict__ A) {
    int row = blockIdx.x * 8 + (threadIdx.x >> 5);
    int lane = threadIdx.x & 31;
    if (row >= g_M) return;
    const float* a = A + (size_t)g_cmap[row] * DIN;
    unsigned short* o = &g_A2[row][0];
    for (int k = lane; k < 320; k += 32) {
        float v = (k < DIN) ? a[k] : 0.f;
        __nv_bfloat16 hb = __float2bfloat16(v);
        __nv_bfloat16 lb = __float2bfloat16(v - __bfloat162float(hb));
        o[k] = bfbits(hb); o[320 + k] = bfbits(lb);
    }
}

// xz weights: B2[l][dir][n][k'] = [Bh|Bl|Bh], B[n][k] = W[k][n]
__global__ void prep_b2_all(const float* __restrict__ fwk, const float* __restrict__ bwk) {
    long long idx = (long long)blockIdx.x * blockDim.x + threadIdx.x;
    const long long total = (long long)DEPTH * 2 * 640 * KPB;
    if (idx >= total) return;
    int l   = (int)(idx / (2LL * 640 * KPB));
    long long r = idx - (long long)l * 2 * 640 * KPB;
    int dir = (int)(r / (640LL * KPB));
    int r2  = (int)(r - (long long)dir * 640 * KPB);
    int n = r2 / KPB, k = r2 - n * KPB;
    int seg = k / 320, kk = k - seg * 320;
    const float* W = (dir ? bwk : fwk) + (size_t)l * 450 * G4;
    float v = (n < G4 && kk < DIN) ? W[(size_t)kk * G4 + n] : 0.f;
    __nv_bfloat16 hb = __float2bfloat16(v);
    unsigned short o;
    if (seg == 1) o = bfbits(__float2bfloat16(v - __bfloat162float(hb)));
    else          o = bfbits(hb);
    g_B2[l][dir][n][k] = o;
}

// recurrent weights: g_WhB[l][dir][n][k'], k'=3k+s: s=1 -> Whl, else Whh
__global__ void prep_whb(const float* __restrict__ fwk, const float* __restrict__ bwk) {
    int idx = blockIdx.x * blockDim.x + threadIdx.x;
    const int total = DEPTH * 2 * 600 * 512;
    if (idx >= total) return;
    int kp = idx & 511;
    int n  = (idx >> 9) % 600;
    int dir = (idx / (512 * 600)) & 1;
    int l   = idx / (512 * 600 * 2);
    unsigned short o = 0;
    if (kp < 450) {
        int k = kp / 3, s = kp - 3 * k;
        const float* W = (dir ? bwk : fwk) + (size_t)l * 450 * G4 + (size_t)(DIN + k) * G4;
        float w = W[n];
        __nv_bfloat16 hb = __float2bfloat16(w);
        if (s == 1) o = bfbits(__float2bfloat16(w - __bfloat162float(hb)));
        else        o = bfbits(hb);
    }
    g_WhB[l][dir][n][kp] = o;
}

// ---------------- tensor-core input projection (3-stage pipeline) --------------
#define XZ_SMEM_SZ (3*32768 + 1024)

__global__ void __launch_bounds__(256, 2) xz_hmma(
    int layer, const float* __restrict__ bf, const float* __restrict__ bb2)
{
    const int Mv = g_M;
    const int m0 = blockIdx.y * 128;
    if (m0 >= Mv) return;
    const int dir = blockIdx.z;
    const int n0 = blockIdx.x * 128;
    const int tid = threadIdx.x;
    const int wid = tid >> 5, lane = tid & 31;

    extern __shared__ char dsm[];
    uint32_t base = (smem_u32(dsm) + 1023) & ~1023u;
    __shared__ int cmi[128];
    if (tid < 128) {
        int gm = m0 + tid;
        cmi[tid] = (gm < Mv) ? g_cmap[gm] : 0;
    }

    const unsigned short* __restrict__ Arow = &g_A2[m0][0];
    const unsigned short* __restrict__ Brow = &g_B2[layer][dir][n0][0];

    auto cp_chunk = [&](int c, int b) {
        uint32_t ab = base + (uint32_t)b * 32768u;
        uint32_t bb = ab + 16384u;
        int akof = (c % 5) * 64 + (c >= 10 ? 320 : 0);   // A2 is [Ah|Al], Ah reused
        int bkof = c * 64;
        #pragma unroll
        for (int i = 0; i < 4; i++) {
            int g2 = tid + i * 256;
            int row = g2 >> 3, gr = g2 & 7;
            uint32_t off = SWZ((uint32_t)(row * 128 + gr * 16));
            cp16(ab + off, Arow + (size_t)row * KPA + akof + gr * 8);
            cp16(bb + off, Brow + (size_t)row * KPB + bkof + gr * 8);
        }
        asm volatile("cp.async.commit_group;" ::: "memory");
    };

    const int wm0 = (wid & 3) * 32;
    const int wn0 = (wid >> 2) * 64;

    float acc[2][8][4];
    #pragma unroll
    for (int mt = 0; mt < 2; mt++)
        #pragma unroll
        for (int nt = 0; nt < 8; nt++)
            #pragma unroll
            for (int e = 0; e < 4; e++) acc[mt][nt][e] = 0.f;

    cp_chunk(0, 0);
    cp_chunk(1, 1);

    for (int c = 0; c < 15; c++) {
        if (c < 14) {
            asm volatile("cp.async.wait_group 1;" ::: "memory");
        } else {
            asm volatile("cp.async.wait_group 0;" ::: "memory");
        }
        __syncthreads();               // chunk c resident; buffer (c+2)%3 free
        if (c + 2 < 15) cp_chunk(c + 2, (c + 2) % 3);

        uint32_t ab = base + (uint32_t)(c % 3) * 32768u;
        uint32_t bb = ab + 16384u;
        #pragma unroll
        for (int ks = 0; ks < 4; ks++) {
            uint32_t afr[2][4];
            #pragma unroll
            for (int mt = 0; mt < 2; mt++) {
                int row = wm0 + mt * 16 + (lane & 15);
                int gr  = ks * 2 + (lane >> 4);
                uint32_t addr = ab + SWZ((uint32_t)(row * 128 + gr * 16));
                LDSM4(afr[mt][0], afr[mt][1], afr[mt][2], afr[mt][3], addr);
            }
            uint32_t bfr[8][2];
            #pragma unroll
            for (int nt4 = 0; nt4 < 4; nt4++) {
                int row = wn0 + nt4 * 16 + (lane & 15);
                int gr  = ks * 2 + (lane >> 4);
                uint32_t addr = bb + SWZ((uint32_t)(row * 128 + gr * 16));
                uint32_t r0, r1, r2, r3;
                LDSM4(r0, r1, r2, r3, addr);
                bfr[nt4*2][0]   = r0; bfr[nt4*2][1]   = r2;
                bfr[nt4*2+1][0] = r1; bfr[nt4*2+1][1] = r3;
            }
            #pragma unroll
            for (int mt = 0; mt < 2; mt++)
                #pragma unroll
                for (int nt = 0; nt < 8; nt++)
                    MMA16816(acc[mt][nt], afr[mt], bfr[nt][0], bfr[nt][1]);
        }
    }

    __syncthreads();
    const float* __restrict__ bias = dir ? bb2 : bf;
    float* __restrict__ outp = &g_xz[dir][0][0];
    #pragma unroll
    for (int mt = 0; mt < 2; mt++) {
        int r_lo = wm0 + mt * 16 + (lane >> 2);
        int r_hi = r_lo + 8;
        bool v_lo = (m0 + r_lo) < Mv, v_hi = (m0 + r_hi) < Mv;
        #pragma unroll
        for (int nt = 0; nt < 8; nt++) {
            int col = n0 + wn0 + nt * 8 + (lane & 3) * 2;
            if (col + 1 < G4) {
                float bx = __ldg(&bias[col]), by = __ldg(&bias[col + 1]);
                if (v_lo) {
                    float2 v = {acc[mt][nt][0] + bx, acc[mt][nt][1] + by};
                    *(float2*)&outp[(size_t)cmi[r_lo] * G4 + col] = v;
                }
                if (v_hi) {
                    float2 v = {acc[mt][nt][2] + bx, acc[mt][nt][3] + by};
                    *(float2*)&outp[(size_t)cmi[r_hi] * G4 + col] = v;
                }
            }
        }
    }
}

// ---------------- persistent per-layer LSTM (mma.sync, R9-proven barrier) ------
// Grid: 128 blocks = dir(2) x btile(8, 128 rows) x hq(8, 20 hidx).
// 640 threads / 20 warps (4m x 5n); warp tile 32 rows x 16 gatecols.
#define LTH2 640
#define SM_A 131072          // 8 chunks x 128 rows x 128B
#define SM_B 81920           // 8 chunks x  80 rows x 128B
#define LSTM2_SMEM (1024 + SM_A + SM_B)
#define KS29 29

__global__ void __launch_bounds__(LTH2, 1) lstm_mma(int layer, int basestep)
{
    extern __shared__ char dsm[];
    uint32_t Ab = (smem_u32(dsm) + 1023) & ~1023u;
    uint32_t Bb = Ab + SM_A;
    char* gA = dsm + (Ab - smem_u32(dsm));
    char* gB = gA + SM_A;

    const int blk   = blockIdx.x;
    const int dir   = blk >> 6;
    const int btile = (blk >> 3) & 7;
    const int hq    = blk & 7;
    const int b0    = btile * 128;
    const int hidx0 = hq * 20;
    const int tid = threadIdx.x;
    const int wid = tid >> 5, lane = tid & 31;
    int* cnt = &g_cnt[(dir * 8 + btile) * 32];

    // zero B smem (covers hidx >= 150 pad rows), then stage weights once
    for (int i = tid; i < SM_B / 16; i += LTH2)
        *(float4*)(gB + i * 16) = make_float4(0, 0, 0, 0);
    __syncthreads();
    for (int i = tid; i < 8 * 80 * 8; i += LTH2) {
        int g = i & 7, r = (i >> 3) % 80, ch = i / 640;
        int hidx = hidx0 + (r >> 2);
        if (hidx < HH) {
            int srow = (r & 3) * HH + hidx;
            cp16(Bb + ch * 10240 + SWZ((uint32_t)(r * 128 + g * 16)),
                 &g_WhB[layer][dir][srow][ch * 64 + g * 8]);
        }
    }
    asm volatile("cp.async.commit_group;" ::: "memory");

    const int wm0 = (wid / 5) * 32;
    const int wn0 = (wid % 5) * 16;

    int rows[2];
    rows[0] = wm0 + (lane >> 2) + ((lane & 1) ? 8 : 0);
    rows[1] = rows[0] + 16;
    int hxs[2];
    hxs[0] = hidx0 + (wid % 5) * 4 + ((lane & 3) >> 1);
    hxs[1] = hxs[0] + 2;

    int len[2], cof[2];
    #pragma unroll
    for (int mt = 0; mt < 2; mt++) {
        len[mt] = g_lens[b0 + rows[mt]];
        cof[mt] = g_coff[b0 + rows[mt]];
    }
    float cst[2][2] = {{0.f, 0.f}, {0.f, 0.f}};

    for (int step = 0; step < TT; step++) {
        // stage A (h in operand form); step 0: h = 0
        if (step == 0) {
            for (int i = tid; i < SM_A / 16; i += LTH2)
                *(float4*)(gA + i * 16) = make_float4(0, 0, 0, 0);
        } else {
            for (int i = tid; i < 8192; i += LTH2) {        // 8ch x 128r x 8g
                int g = i & 7, r = (i >> 3) & 127, ch = i >> 10;
                cp16(Ab + ch * 16384 + SWZ((uint32_t)(r * 128 + g * 16)),
                     &g_hA[dir][b0 + r][ch * 64 + g * 8]);
            }
            asm volatile("cp.async.commit_group;" ::: "memory");
        }
        asm volatile("cp.async.wait_group 0;" ::: "memory");
        __syncthreads();

        // prefetch xz gate biases
        float xzv[2][2][4];
        int trow[2];
        #pragma unroll
        for (int mt = 0; mt < 2; mt++) {
            if (step < len[mt]) {
                trow[mt] = dir ? (len[mt] - 1 - step) : step;
                const float* __restrict__ xz =
                    &g_xz[dir][(b0 + rows[mt]) * TT + trow[mt]][0];
                #pragma unroll
                for (int nt = 0; nt < 2; nt++) {
                    if (hxs[nt] < HH) {
                        #pragma unroll
                        for (int g = 0; g < 4; g++)
                            xzv[mt][nt][g] = __ldg(&xz[g * HH + hxs[nt]]);
                    }
                }
            }
        }

        // GEMM: h @ Wh
        float acc[2][2][4];
        #pragma unroll
        for (int mt = 0; mt < 2; mt++)
            #pragma unroll
            for (int nt = 0; nt < 2; nt++)
                #pragma unroll
                for (int e = 0; e < 4; e++) acc[mt][nt][e] = 0.f;

        #pragma unroll
        for (int ks = 0; ks < KS29; ks++) {
            int ch = ks >> 2, ik = ks & 3;
            uint32_t afr[2][4];
            #pragma unroll
            for (int mt = 0; mt < 2; mt++) {
                int row = wm0 + mt * 16 + (lane & 15);
                uint32_t addr = Ab + ch * 16384 +
                    SWZ((uint32_t)(row * 128 + ik * 32 + (lane >> 4) * 16));
                LDSM4(afr[mt][0], afr[mt][1], afr[mt][2], afr[mt][3], addr);
            }
            int brow = wn0 + (lane & 15);
            uint32_t baddr = Bb + ch * 10240 +
                SWZ((uint32_t)(brow * 128 + ik * 32 + (lane >> 4) * 16));
            uint32_t r0, r1, r2, r3;
            LDSM4(r0, r1, r2, r3, baddr);
            #pragma unroll
            for (int mt = 0; mt < 2; mt++) {
                MMA16816(acc[mt][0], afr[mt], r0, r2);
                MMA16816(acc[mt][1], afr[mt], r1, r3);
            }
        }

        // epilogue: gather gates via shfl, LSTM update, write operands
        #pragma unroll
        for (int mt = 0; mt < 2; mt++) {
            #pragma unroll
            for (int nt = 0; nt < 2; nt++) {
                float c0 = acc[mt][nt][0], c1 = acc[mt][nt][1];
                float c2 = acc[mt][nt][2], c3 = acc[mt][nt][3];
                float ex0 = __shfl_xor_sync(0xffffffffu, c0, 1);
                float ex1 = __shfl_xor_sync(0xffffffffu, c1, 1);
                float ex2 = __shfl_xor_sync(0xffffffffu, c2, 1);
                float ex3 = __shfl_xor_sync(0xffffffffu, c3, 1);
                float zi, zj, zf, zo;
                if ((lane & 1) == 0) { zi = c0;  zj = c1;  zf = ex0; zo = ex1; }
                else                 { zi = ex2; zj = ex3; zf = c2;  zo = c3;  }
                if (step < len[mt] && hxs[nt] < HH) {
                    zi += xzv[mt][nt][0];
                    zj += xzv[mt][nt][1];
                    zf += xzv[mt][nt][2];
                    zo += xzv[mt][nt][3];
                    float c  = cst[mt][nt];
                    float cn = c * sigmf(zf + 1.0f) + sigmf(zi) * tanhff(zj);
                    float hn = tanhff(cn) * sigmf(zo);
                    cst[mt][nt] = cn;
                    int b = b0 + rows[mt], hidx = hxs[nt];
                    __nv_bfloat16 hb = __float2bfloat16(hn);
                    unsigned short hu = bfbits(hb);
                    unsigned short lu =
                        bfbits(__float2bfloat16(hn - __bfloat162float(hb)));
                    unsigned short* hp = &g_hA[dir][b][3 * hidx];
                    hp[0] = hu; hp[1] = hu; hp[2] = lu;
                    int arow = cof[mt] + trow[mt];
                    int cd = dir * HH + hidx;
                    unsigned short* ar = &g_A2[arow][0];
                    ar[cd] = hu; ar[320 + cd] = lu;
                }
            }
        }

        // 8-block group barrier (release folds the fence; acquire invalidates L1)
        __syncthreads();
        if (tid == 0) {
            asm volatile("red.release.gpu.global.add.s32 [%0], 1;"
                         :: "l"(cnt) : "memory");
            int target = 8 * (basestep + step + 1);
            int v;
            do {
                asm volatile("ld.acquire.gpu.global.b32 %0, [%1];"
                             : "=r"(v) : "l"(cnt) : "memory");
            } while (v < target);
        }
        __syncthreads();
    }
}

// ---------------- classifier head (reads split-bf16 A2) ------------------------
__global__ void classify(const float* __restrict__ dW, const float* __restrict__ db,
                         const float* __restrict__ W,  const float* __restrict__ bb,
                         float* __restrict__ out, int out_size)
{
    int b = blockIdx.x;
    __shared__ float xin[DIN];
    __shared__ float hvec[HH];
    __shared__ float lg[2];
    int len = g_lens[b];
    int row = g_coff[b] + len - 1;
    const unsigned short* ar = &g_A2[row][0];
    for (int i = threadIdx.x; i < DIN; i += blockDim.x)
        xin[i] = bf2f(ar[i]) + bf2f(ar[320 + i]);
    __syncthreads();
    for (int j = threadIdx.x; j < HH; j += blockDim.x) {
        float s = db[j];
        #pragma unroll 4
        for (int k = 0; k < DIN; k++) s = fmaf(xin[k], dW[k * HH + j], s);
        hvec[j] = fmaxf(s, 0.f);
    }
    __syncthreads();
    if (threadIdx.x < 2) {
        float s = bb[threadIdx.x];
        for (int k = 0; k < HH; k++) s = fmaf(hvec[k], W[k * 2 + threadIdx.x], s);
        lg[threadIdx.x] = s;
    }
    __syncthreads();
    if (threadIdx.x == 0) {
        float l0 = lg[0], l1 = lg[1];
        float pred = (l1 > l0) ? 1.f : 0.f;
        if (out_size >= 3 * BB) {
            out[b * 2 + 0] = l0; out[b * 2 + 1] = l1;
            out[2 * BB + b] = pred;
        } else if (out_size >= 2 * BB) {
            out[b * 2 + 0] = l0; out[b * 2 + 1] = l1;
        } else {
            out[b] = pred;
        }
    }
}

// ---------------- launch ------------------------------------------------------
extern "C" void kernel_launch(void* const* d_in, const int* in_sizes, int n_in,
                              void* d_out, int out_size)
{
    const float* X    = (const float*)d_in[0];
    const int*   mask = (const int*)  d_in[1];
    const float* fwk  = (const float*)d_in[2];
    const float* fwb  = (const float*)d_in[3];
    const float* bwk  = (const float*)d_in[4];
    const float* bwb  = (const float*)d_in[5];
    const float* dW   = (const float*)d_in[6];
    const float* db   = (const float*)d_in[7];
    const float* W    = (const float*)d_in[8];
    const float* bb   = (const float*)d_in[9];
    float* out = (float*)d_out;

    static int configured = 0;
    if (!configured) {
        cudaFuncSetAttribute(xz_hmma,  cudaFuncAttributeMaxDynamicSharedMemorySize, XZ_SMEM_SZ);
        cudaFuncSetAttribute(lstm_mma, cudaFuncAttributeMaxDynamicSharedMemorySize, LSTM2_SMEM);
        configured = 1;
    }

    build_cmap<<<1, 1024>>>(mask);

    const long long b2_total = (long long)DEPTH * 2 * 640 * KPB;
    prep_b2_all<<<(int)((b2_total + 255) / 256), 256>>>(fwk, bwk);
    prep_whb<<<(DEPTH * 2 * 600 * 512 + 255) / 256, 256>>>(fwk, bwk);
    prep_a2<<<BT / 8, 256>>>(X);

    for (int l = 0; l < DEPTH; l++) {
        xz_hmma<<<dim3(5, 560, 2), 256, XZ_SMEM_SZ>>>(l, fwb + l * G4, bwb + l * G4);
        lstm_mma<<<128, LTH2, LSTM2_SMEM>>>(l, l * TT);
    }
    classify<<<BB, 256>>>(dW, db, W, bb, out, out_size);
}

// round 14
// speedup vs baseline: 1.1719x; 1.1719x over previous
#include <cuda_runtime.h>
#include <cuda_bf16.h>
#include <math.h>
#include <stdint.h>

#define BB 1024
#define TT 70
#define HH 150
#define DIN 300
#define G4 600
#define BT (BB*TT)
#define DEPTH 5
#define KPA 640           // A2: [Ah(320) | Al(320)]
#define KPB 960           // B2: [Bh | Bl | Bh]

typedef unsigned long long ull;

// ---------------- scratch ----------------------------------------------------
__device__ float g_xz[2][BT][G4];
__device__ int   g_lens[BB];
__device__ int   g_coff[BB];
__device__ int   g_cnt[32*32];
__device__ int   g_cmap[BT];
__device__ int   g_M;
__device__ unsigned short g_A2[BT][KPA];            // split-bf16 activations
__device__ unsigned short g_B2[DEPTH][2][640][KPB]; // xz weights (split-bf16, W^T)
__device__ unsigned short g_hA[2][BB][512];         // h in interleaved-3 operand form
__device__ unsigned short g_WhB[DEPTH][2][600][512];// recurrent weights interleaved-3

// ---------------- helpers -----------------------------------------------------
__device__ __forceinline__ float sigmf(float x) {
    return __fdividef(1.f, 1.f + __expf(-x));
}
__device__ __forceinline__ float tanhff(float x) {
    return 1.f - __fdividef(2.f, __expf(2.f * x) + 1.f);
}
__device__ __forceinline__ void cp16(uint32_t smem_dst, const void* gsrc) {
    asm volatile("cp.async.ca.shared.global [%0], [%1], 16;"
                 :: "r"(smem_dst), "l"(gsrc) : "memory");
}
__device__ __forceinline__ uint32_t smem_u32(const void* p) {
    uint32_t a;
    asm("{ .reg .u64 t; cvta.to.shared.u64 t, %1; cvt.u32.u64 %0, t; }"
        : "=r"(a) : "l"(p));
    return a;
}
#define SWZ(o) ((o) ^ (((o) >> 3) & 0x70))

#define LDSM4(r0,r1,r2,r3,addr) \
    asm volatile("ldmatrix.sync.aligned.m8n8.x4.shared.b16 {%0,%1,%2,%3}, [%4];" \
        : "=r"(r0), "=r"(r1), "=r"(r2), "=r"(r3) : "r"(addr))

#define MMA16816(c,a,b0,b1) \
    asm volatile("mma.sync.aligned.m16n8k16.row.col.f32.bf16.bf16.f32 " \
        "{%0,%1,%2,%3}, {%4,%5,%6,%7}, {%8,%9}, {%0,%1,%2,%3};" \
        : "+f"((c)[0]), "+f"((c)[1]), "+f"((c)[2]), "+f"((c)[3]) \
        : "r"((a)[0]), "r"((a)[1]), "r"((a)[2]), "r"((a)[3]), "r"(b0), "r"(b1))

__device__ __forceinline__ unsigned short bfbits(__nv_bfloat16 h) {
    return *(unsigned short*)&h;
}
__device__ __forceinline__ float bf2f(unsigned short u) {
    __nv_bfloat16 h = *(__nv_bfloat16*)&u;
    return __bfloat162float(h);
}

// ---------------- lens + scan + cmap -----------------------------------------
__global__ void build_cmap(const int* __restrict__ mask) {
    __shared__ int sl[1024];
    int b = threadIdx.x;
    int s = 0;
    #pragma unroll
    for (int t = 0; t < TT; t++) s += mask[b * TT + t];
    g_lens[b] = s;
    sl[b] = s;
    g_cnt[b] = 0;
    __syncthreads();
    for (int d = 1; d < 1024; d <<= 1) {
        int v = 0;
        if (b >= d) v = sl[b - d];
        __syncthreads();
        if (b >= d) sl[b] += v;
        __syncthreads();
    }
    int excl = sl[b] - s;
    g_coff[b] = excl;
    for (int t = 0; t < s; t++) g_cmap[excl + t] = b * TT + t;
    if (b == 1023) g_M = sl[1023];
}

// ---------------- operand prep ------------------------------------------------
// Layer 0 A2 from X: identity column map (k = input dim), pads zero.
__global__ void prep_a2(const float* __restrict__ A) {
    int row = blockIdx.x * 8 + (threadIdx.x >> 5);
    int lane = threadIdx.x & 31;
    if (row >= g_M) return;
    const float* a = A + (size_t)g_cmap[row] * DIN;
    unsigned short* o = &g_A2[row][0];
    for (int k = lane; k < 320; k += 32) {
        float v = (k < DIN) ? a[k] : 0.f;
        __nv_bfloat16 hb = __float2bfloat16(v);
        __nv_bfloat16 lb = __float2bfloat16(v - __bfloat162float(hb));
        o[k] = bfbits(hb); o[320 + k] = bfbits(lb);
    }
}

// xz weights. Layer 0: identity input map. Layers>0: A2 cols are
// [fw h: 0..149 | pad | bw h: 160..309 | pad] -> remap kk accordingly.
__global__ void prep_b2_all(const float* __restrict__ fwk, const float* __restrict__ bwk) {
    long long idx = (long long)blockIdx.x * blockDim.x + threadIdx.x;
    const long long total = (long long)DEPTH * 2 * 640 * KPB;
    if (idx >= total) return;
    int l   = (int)(idx / (2LL * 640 * KPB));
    long long r = idx - (long long)l * 2 * 640 * KPB;
    int dir = (int)(r / (640LL * KPB));
    int r2  = (int)(r - (long long)dir * 640 * KPB);
    int n = r2 / KPB, k = r2 - n * KPB;
    int seg = k / 320, kk = k - seg * 320;
    int j = 0; bool valid = (n < G4);
    if (l == 0) {
        if (kk < DIN) j = kk; else valid = false;
    } else {
        if (kk < 150) j = kk;
        else if (kk >= 160 && kk < 310) j = kk - 10;
        else valid = false;
    }
    const float* W = (dir ? bwk : fwk) + (size_t)l * 450 * G4;
    float v = valid ? W[(size_t)j * G4 + n] : 0.f;
    __nv_bfloat16 hb = __float2bfloat16(v);
    unsigned short o;
    if (seg == 1) o = bfbits(__float2bfloat16(v - __bfloat162float(hb)));
    else          o = bfbits(hb);
    g_B2[l][dir][n][k] = o;
}

// recurrent weights: g_WhB[l][dir][n][k'], k'=3k+s: s=1 -> Whl, else Whh
__global__ void prep_whb(const float* __restrict__ fwk, const float* __restrict__ bwk) {
    int idx = blockIdx.x * blockDim.x + threadIdx.x;
    const int total = DEPTH * 2 * 600 * 512;
    if (idx >= total) return;
    int kp = idx & 511;
    int n  = (idx >> 9) % 600;
    int dir = (idx / (512 * 600)) & 1;
    int l   = idx / (512 * 600 * 2);
    unsigned short o = 0;
    if (kp < 450) {
        int k = kp / 3, s = kp - 3 * k;
        const float* W = (dir ? bwk : fwk) + (size_t)l * 450 * G4 + (size_t)(DIN + k) * G4;
        float w = W[n];
        __nv_bfloat16 hb = __float2bfloat16(w);
        if (s == 1) o = bfbits(__float2bfloat16(w - __bfloat162float(hb)));
        else        o = bfbits(hb);
    }
    g_WhB[l][dir][n][kp] = o;
}

// ---------------- tensor-core input projection (2-stage, R9-proven) ------------
#define XZ_SMEM_SZ (2*32768 + 1024)

__global__ void __launch_bounds__(256, 2) xz_hmma(
    int layer, const float* __restrict__ bf, const float* __restrict__ bb2)
{
    const int Mv = g_M;
    const int m0 = blockIdx.y * 128;
    if (m0 >= Mv) return;
    const int dir = blockIdx.z;
    const int n0 = blockIdx.x * 128;
    const int tid = threadIdx.x;
    const int wid = tid >> 5, lane = tid & 31;

    extern __shared__ char dsm[];
    uint32_t base = (smem_u32(dsm) + 1023) & ~1023u;
    __shared__ int cmi[128];
    if (tid < 128) {
        int gm = m0 + tid;
        cmi[tid] = (gm < Mv) ? g_cmap[gm] : 0;
    }

    const unsigned short* __restrict__ Arow = &g_A2[m0][0];
    const unsigned short* __restrict__ Brow = &g_B2[layer][dir][n0][0];

    auto cp_chunk = [&](int c, int b) {
        uint32_t ab = base + (uint32_t)b * 32768u;
        uint32_t bb = ab + 16384u;
        int akof = (c % 5) * 64 + (c >= 10 ? 320 : 0);   // A2 is [Ah|Al], Ah reused
        int bkof = c * 64;
        #pragma unroll
        for (int i = 0; i < 4; i++) {
            int g2 = tid + i * 256;
            int row = g2 >> 3, gr = g2 & 7;
            uint32_t off = SWZ((uint32_t)(row * 128 + gr * 16));
            cp16(ab + off, Arow + (size_t)row * KPA + akof + gr * 8);
            cp16(bb + off, Brow + (size_t)row * KPB + bkof + gr * 8);
        }
        asm volatile("cp.async.commit_group;" ::: "memory");
    };

    const int wm0 = (wid & 3) * 32;
    const int wn0 = (wid >> 2) * 64;

    float acc[2][8][4];
    #pragma unroll
    for (int mt = 0; mt < 2; mt++)
        #pragma unroll
        for (int nt = 0; nt < 8; nt++)
            #pragma unroll
            for (int e = 0; e < 4; e++) acc[mt][nt][e] = 0.f;

    cp_chunk(0, 0);

    for (int c = 0; c < 15; c++) {
        if (c + 1 < 15) {
            cp_chunk(c + 1, (c + 1) & 1);
            asm volatile("cp.async.wait_group 1;" ::: "memory");
        } else {
            asm volatile("cp.async.wait_group 0;" ::: "memory");
        }
        __syncthreads();

        uint32_t ab = base + (uint32_t)(c & 1) * 32768u;
        uint32_t bb = ab + 16384u;
        #pragma unroll
        for (int ks = 0; ks < 4; ks++) {
            uint32_t afr[2][4];
            #pragma unroll
            for (int mt = 0; mt < 2; mt++) {
                int row = wm0 + mt * 16 + (lane & 15);
                int gr  = ks * 2 + (lane >> 4);
                uint32_t addr = ab + SWZ((uint32_t)(row * 128 + gr * 16));
                LDSM4(afr[mt][0], afr[mt][1], afr[mt][2], afr[mt][3], addr);
            }
            uint32_t bfr[8][2];
            #pragma unroll
            for (int nt4 = 0; nt4 < 4; nt4++) {
                int row = wn0 + nt4 * 16 + (lane & 15);
                int gr  = ks * 2 + (lane >> 4);
                uint32_t addr = bb + SWZ((uint32_t)(row * 128 + gr * 16));
                uint32_t r0, r1, r2, r3;
                LDSM4(r0, r1, r2, r3, addr);
                bfr[nt4*2][0]   = r0; bfr[nt4*2][1]   = r2;
                bfr[nt4*2+1][0] = r1; bfr[nt4*2+1][1] = r3;
            }
            #pragma unroll
            for (int mt = 0; mt < 2; mt++)
                #pragma unroll
                for (int nt = 0; nt < 8; nt++)
                    MMA16816(acc[mt][nt], afr[mt], bfr[nt][0], bfr[nt][1]);
        }
        __syncthreads();
    }

    const float* __restrict__ bias = dir ? bb2 : bf;
    float* __restrict__ outp = &g_xz[dir][0][0];
    #pragma unroll
    for (int mt = 0; mt < 2; mt++) {
        int r_lo = wm0 + mt * 16 + (lane >> 2);
        int r_hi = r_lo + 8;
        bool v_lo = (m0 + r_lo) < Mv, v_hi = (m0 + r_hi) < Mv;
        #pragma unroll
        for (int nt = 0; nt < 8; nt++) {
            int col = n0 + wn0 + nt * 8 + (lane & 3) * 2;
            if (col + 1 < G4) {
                float bx = __ldg(&bias[col]), by = __ldg(&bias[col + 1]);
                if (v_lo) {
                    float2 v = {acc[mt][nt][0] + bx, acc[mt][nt][1] + by};
                    *(float2*)&outp[(size_t)cmi[r_lo] * G4 + col] = v;
                }
                if (v_hi) {
                    float2 v = {acc[mt][nt][2] + bx, acc[mt][nt][3] + by};
                    *(float2*)&outp[(size_t)cmi[r_hi] * G4 + col] = v;
                }
            }
        }
    }
}

// ---------------- persistent per-layer LSTM (mma.sync, coalesced epilogue) -----
// Grid: 128 blocks = dir(2) x btile(8, 128 rows) x hq(8, 20 hidx).
// 640 threads / 20 warps (4m x 5n); warp tile 32 rows x 16 gatecols.
// Epilogue stages hu/lu in smem; cooperative writers emit coalesced u32 runs.
#define LTH2 640
#define SM_A 131072          // 8 chunks x 128 rows x 128B
#define SM_B 81920           // 8 chunks x  80 rows x 128B
#define SM_G 10240           // sAh + sAl: 2 x 128 x 20 shorts
#define LSTM2_SMEM (1024 + SM_A + SM_B + SM_G)
#define KS29 29

__global__ void __launch_bounds__(LTH2, 1) lstm_mma(int layer, int basestep)
{
    extern __shared__ char dsm[];
    uint32_t Ab = (smem_u32(dsm) + 1023) & ~1023u;
    uint32_t Bb = Ab + SM_A;
    char* gA = dsm + (Ab - smem_u32(dsm));
    char* gB = gA + SM_A;
    unsigned short* sAh = (unsigned short*)(gB + SM_B);       // [128][20]
    unsigned short* sAl = sAh + 128 * 20;                     // [128][20]
    __shared__ int slen[128];
    __shared__ int scoff[128];

    const int blk   = blockIdx.x;
    const int dir   = blk >> 6;
    const int btile = (blk >> 3) & 7;
    const int hq    = blk & 7;
    const int b0    = btile * 128;
    const int hidx0 = hq * 20;
    const int tid = threadIdx.x;
    const int wid = tid >> 5, lane = tid & 31;
    int* cnt = &g_cnt[(dir * 8 + btile) * 32];

    if (tid < 128) {
        slen[tid]  = g_lens[b0 + tid];
        scoff[tid] = g_coff[b0 + tid];
    }

    // zero B smem (covers hidx >= 150 pad rows), then stage weights once
    for (int i = tid; i < SM_B / 16; i += LTH2)
        *(float4*)(gB + i * 16) = make_float4(0, 0, 0, 0);
    __syncthreads();
    for (int i = tid; i < 8 * 80 * 8; i += LTH2) {
        int g = i & 7, r = (i >> 3) % 80, ch = i / 640;
        int hidx = hidx0 + (r >> 2);
        if (hidx < HH) {
            int srow = (r & 3) * HH + hidx;
            cp16(Bb + ch * 10240 + SWZ((uint32_t)(r * 128 + g * 16)),
                 &g_WhB[layer][dir][srow][ch * 64 + g * 8]);
        }
    }
    asm volatile("cp.async.commit_group;" ::: "memory");

    const int wm0 = (wid / 5) * 32;
    const int wn0 = (wid % 5) * 16;

    int rows[2];
    rows[0] = wm0 + (lane >> 2) + ((lane & 1) ? 8 : 0);
    rows[1] = rows[0] + 16;
    int hxs[2];
    hxs[0] = hidx0 + (wid % 5) * 4 + ((lane & 3) >> 1);
    hxs[1] = hxs[0] + 2;

    int len[2];
    #pragma unroll
    for (int mt = 0; mt < 2; mt++) len[mt] = g_lens[b0 + rows[mt]];

    float cst[2][2] = {{0.f, 0.f}, {0.f, 0.f}};
    unsigned short hcu[2][2] = {{0,0},{0,0}};   // carried bf16-hi of h
    unsigned short hcl[2][2] = {{0,0},{0,0}};   // carried bf16-lo of h

    for (int step = 0; step < TT; step++) {
        // stage A (h in operand form); step 0: h = 0
        if (step == 0) {
            for (int i = tid; i < SM_A / 16; i += LTH2)
                *(float4*)(gA + i * 16) = make_float4(0, 0, 0, 0);
        } else {
            for (int i = tid; i < 8192; i += LTH2) {        // 8ch x 128r x 8g
                int g = i & 7, r = (i >> 3) & 127, ch = i >> 10;
                cp16(Ab + ch * 16384 + SWZ((uint32_t)(r * 128 + g * 16)),
                     &g_hA[dir][b0 + r][ch * 64 + g * 8]);
            }
            asm volatile("cp.async.commit_group;" ::: "memory");
        }
        asm volatile("cp.async.wait_group 0;" ::: "memory");
        __syncthreads();

        // prefetch xz gate biases
        float xzv[2][2][4];
        #pragma unroll
        for (int mt = 0; mt < 2; mt++) {
            if (step < len[mt]) {
                int t = dir ? (len[mt] - 1 - step) : step;
                const float* __restrict__ xz =
                    &g_xz[dir][(b0 + rows[mt]) * TT + t][0];
                #pragma unroll
                for (int nt = 0; nt < 2; nt++) {
                    if (hxs[nt] < HH) {
                        #pragma unroll
                        for (int g = 0; g < 4; g++)
                            xzv[mt][nt][g] = __ldg(&xz[g * HH + hxs[nt]]);
                    }
                }
            }
        }

        // GEMM: h @ Wh
        float acc[2][2][4];
        #pragma unroll
        for (int mt = 0; mt < 2; mt++)
            #pragma unroll
            for (int nt = 0; nt < 2; nt++)
                #pragma unroll
                for (int e = 0; e < 4; e++) acc[mt][nt][e] = 0.f;

        #pragma unroll
        for (int ks = 0; ks < KS29; ks++) {
            int ch = ks >> 2, ik = ks & 3;
            uint32_t afr[2][4];
            #pragma unroll
            for (int mt = 0; mt < 2; mt++) {
                int row = wm0 + mt * 16 + (lane & 15);
                uint32_t addr = Ab + ch * 16384 +
                    SWZ((uint32_t)(row * 128 + ik * 32 + (lane >> 4) * 16));
                LDSM4(afr[mt][0], afr[mt][1], afr[mt][2], afr[mt][3], addr);
            }
            int brow = wn0 + (lane & 15);
            uint32_t baddr = Bb + ch * 10240 +
                SWZ((uint32_t)(brow * 128 + ik * 32 + (lane >> 4) * 16));
            uint32_t r0, r1, r2, r3;
            LDSM4(r0, r1, r2, r3, baddr);
            #pragma unroll
            for (int mt = 0; mt < 2; mt++) {
                MMA16816(acc[mt][0], afr[mt], r0, r2);
                MMA16816(acc[mt][1], afr[mt], r1, r3);
            }
        }

        // epilogue: gather gates via shfl, LSTM update, stage hu/lu in smem
        #pragma unroll
        for (int mt = 0; mt < 2; mt++) {
            #pragma unroll
            for (int nt = 0; nt < 2; nt++) {
                float c0 = acc[mt][nt][0], c1 = acc[mt][nt][1];
                float c2 = acc[mt][nt][2], c3 = acc[mt][nt][3];
                float ex0 = __shfl_xor_sync(0xffffffffu, c0, 1);
                float ex1 = __shfl_xor_sync(0xffffffffu, c1, 1);
                float ex2 = __shfl_xor_sync(0xffffffffu, c2, 1);
                float ex3 = __shfl_xor_sync(0xffffffffu, c3, 1);
                float zi, zj, zf, zo;
                if ((lane & 1) == 0) { zi = c0;  zj = c1;  zf = ex0; zo = ex1; }
                else                 { zi = ex2; zj = ex3; zf = c2;  zo = c3;  }
                if (step < len[mt] && hxs[nt] < HH) {
                    zi += xzv[mt][nt][0];
                    zj += xzv[mt][nt][1];
                    zf += xzv[mt][nt][2];
                    zo += xzv[mt][nt][3];
                    float c  = cst[mt][nt];
                    float cn = c * sigmf(zf + 1.0f) + sigmf(zi) * tanhff(zj);
                    float hn = tanhff(cn) * sigmf(zo);
                    cst[mt][nt] = cn;
                    __nv_bfloat16 hb = __float2bfloat16(hn);
                    hcu[mt][nt] = bfbits(hb);
                    hcl[mt][nt] =
                        bfbits(__float2bfloat16(hn - __bfloat162float(hb)));
                }
                int hl = hxs[nt] - hidx0;
                sAh[rows[mt] * 20 + hl] = hcu[mt][nt];
                sAl[rows[mt] * 20 + hl] = hcl[mt][nt];
            }
        }
        __syncthreads();

        // coalesced writer: g_hA (interleaved-3 on the fly), 30 u32 per row
        for (int i = tid; i < 128 * 30; i += LTH2) {
            int r = i / 30, w = i - r * 30;
            int s0 = 2 * w, s1 = s0 + 1;
            int i0 = s0 / 3, sel0 = s0 - 3 * i0;
            int i1 = s1 / 3, sel1 = s1 - 3 * i1;
            unsigned short v0 = (sel0 < 2) ? sAh[r * 20 + i0] : sAl[r * 20 + i0];
            unsigned short v1 = (sel1 < 2) ? sAh[r * 20 + i1] : sAl[r * 20 + i1];
            *(uint32_t*)(&g_hA[dir][b0 + r][0] + hidx0 * 3 + s0) =
                (uint32_t)v0 | ((uint32_t)v1 << 16);
        }

        // coalesced writer: g_A2, one thread per (row, u32-pair): hu + lu segs
        for (int i = tid; i < 128 * 10; i += LTH2) {
            int r = i / 10, q = i - r * 10;
            int sl2 = slen[r];
            if (step < sl2) {
                int hl = 2 * q;
                if (hidx0 + hl < HH) {
                    int t = dir ? (sl2 - 1 - step) : step;
                    int arow = scoff[r] + t;
                    uint32_t vh = (uint32_t)sAh[r * 20 + hl] |
                                  ((uint32_t)sAh[r * 20 + hl + 1] << 16);
                    uint32_t vl = (uint32_t)sAl[r * 20 + hl] |
                                  ((uint32_t)sAl[r * 20 + hl + 1] << 16);
                    int colb = dir * 160 + hidx0 + hl;
                    *(uint32_t*)&g_A2[arow][colb]       = vh;
                    *(uint32_t*)&g_A2[arow][320 + colb] = vl;
                }
            }
        }

        // 8-block group barrier (R9-proven)
        __threadfence();
        __syncthreads();
        if (tid == 0) {
            atomicAdd(cnt, 1);
            int target = 8 * (basestep + step + 1);
            int v;
            do {
                asm volatile("ld.acquire.gpu.global.b32 %0, [%1];"
                             : "=r"(v) : "l"(cnt) : "memory");
            } while (v < target);
        }
        __syncthreads();
    }
}

// ---------------- classifier head (reads split-bf16 A2, remapped cols) ---------
__global__ void classify(const float* __restrict__ dW, const float* __restrict__ db,
                         const float* __restrict__ W,  const float* __restrict__ bb,
                         float* __restrict__ out, int out_size)
{
    int b = blockIdx.x;
    __shared__ float xin[DIN];
    __shared__ float hvec[HH];
    __shared__ float lg[2];
    int len = g_lens[b];
    int row = g_coff[b] + len - 1;
    const unsigned short* ar = &g_A2[row][0];
    for (int i = threadIdx.x; i < DIN; i += blockDim.x) {
        int k = (i < 150) ? i : i + 10;
        xin[i] = bf2f(ar[k]) + bf2f(ar[320 + k]);
    }
    __syncthreads();
    for (int j = threadIdx.x; j < HH; j += blockDim.x) {
        float s = db[j];
        #pragma unroll 4
        for (int k = 0; k < DIN; k++) s = fmaf(xin[k], dW[k * HH + j], s);
        hvec[j] = fmaxf(s, 0.f);
    }
    __syncthreads();
    if (threadIdx.x < 2) {
        float s = bb[threadIdx.x];
        for (int k = 0; k < HH; k++) s = fmaf(hvec[k], W[k * 2 + threadIdx.x], s);
        lg[threadIdx.x] = s;
    }
    __syncthreads();
    if (threadIdx.x == 0) {
        float l0 = lg[0], l1 = lg[1];
        float pred = (l1 > l0) ? 1.f : 0.f;
        if (out_size >= 3 * BB) {
            out[b * 2 + 0] = l0; out[b * 2 + 1] = l1;
            out[2 * BB + b] = pred;
        } else if (out_size >= 2 * BB) {
            out[b * 2 + 0] = l0; out[b * 2 + 1] = l1;
        } else {
            out[b] = pred;
        }
    }
}

// ---------------- launch ------------------------------------------------------
extern "C" void kernel_launch(void* const* d_in, const int* in_sizes, int n_in,
                              void* d_out, int out_size)
{
    const float* X    = (const float*)d_in[0];
    const int*   mask = (const int*)  d_in[1];
    const float* fwk  = (const float*)d_in[2];
    const float* fwb  = (const float*)d_in[3];
    const float* bwk  = (const float*)d_in[4];
    const float* bwb  = (const float*)d_in[5];
    const float* dW   = (const float*)d_in[6];
    const float* db   = (const float*)d_in[7];
    const float* W    = (const float*)d_in[8];
    const float* bb   = (const float*)d_in[9];
    float* out = (float*)d_out;

    static int configured = 0;
    if (!configured) {
        cudaFuncSetAttribute(xz_hmma,  cudaFuncAttributeMaxDynamicSharedMemorySize, XZ_SMEM_SZ);
        cudaFuncSetAttribute(lstm_mma, cudaFuncAttributeMaxDynamicSharedMemorySize, LSTM2_SMEM);
        configured = 1;
    }

    build_cmap<<<1, 1024>>>(mask);

    const long long b2_total = (long long)DEPTH * 2 * 640 * KPB;
    prep_b2_all<<<(int)((b2_total + 255) / 256), 256>>>(fwk, bwk);
    prep_whb<<<(DEPTH * 2 * 600 * 512 + 255) / 256, 256>>>(fwk, bwk);
    prep_a2<<<BT / 8, 256>>>(X);

    for (int l = 0; l < DEPTH; l++) {
        xz_hmma<<<dim3(5, 560, 2), 256, XZ_SMEM_SZ>>>(l, fwb + l * G4, bwb + l * G4);
        lstm_mma<<<128, LTH2, LSTM2_SMEM>>>(l, l * TT);
    }
    classify<<<BB, 256>>>(dW, db, W, bb, out, out_size);
}